// round 13
// baseline (speedup 1.0000x reference)
#include <cuda_runtime.h>
#include <math.h>
#include <stdint.h>

#define B 2048
#define C 50257
#define THREADS 512
#define OCC 2
#define NBLK (148 * OCC)        // persistent, all wave-1 resident at 2 CTAs/SM
#define NWARP (THREADS / 32)
// Guaranteed in-bounds unrolled region: n4 >= 12563 for every row alignment.
// 3 iterations x (8*THREADS) float4 = 12288 <= 12563.
#define FULL_ITERS 3
#define FULL_F4 (FULL_ITERS * 8 * THREADS)

// Per-row partials + completion counter (device globals: allocation-guard-safe)
__device__ float g_l1[B];
__device__ float g_ce[B];
__device__ unsigned int g_count = 0;   // self-resetting via atomicInc wrap

__device__ __forceinline__ void elem(float x, float& sum, float& l1, float& es) {
    sum += x;
    l1 += fabsf(1.f - fmaxf(x, 0.f));   // == (x>0) ? |1-x| : 1  (exact)
    es += __expf(x);
}

__device__ __forceinline__ void elem4(const float4 v, float& s0, float& s1,
                                      float& l0, float& l1, float& e0, float& e1) {
    elem(v.x, s0, l0, e0);
    elem(v.y, s1, l1, e1);
    elem(v.z, s0, l0, e0);
    elem(v.w, s1, l1, e1);
}

__device__ __forceinline__ float wred(float v) {
    v += __shfl_xor_sync(0xffffffffu, v, 16);
    v += __shfl_xor_sync(0xffffffffu, v, 8);
    v += __shfl_xor_sync(0xffffffffu, v, 4);
    v += __shfl_xor_sync(0xffffffffu, v, 2);
    v += __shfl_xor_sync(0xffffffffu, v, 1);
    return v;
}

__global__ __launch_bounds__(THREADS, OCC)
void fused_kernel(const float* __restrict__ out, const int* __restrict__ labels,
                  float* __restrict__ res) {
    const int tid  = threadIdx.x;
    const int wid  = tid >> 5;
    const int lane = tid & 31;

    __shared__ float sh_a[NWARP];
    __shared__ float sh_b[NWARP];
    __shared__ float sh_c[NWARP];

    for (int row = blockIdx.x; row < B; row += NBLK) {
        const float* rp = out + (long long)row * C;

        // Prefetch label + gathered logit early (only tid 0 needs them at the end)
        float g = 0.f;
        if (tid == 0) {
            g = __ldg(rp + __ldg(labels + row));
        }

        float sum0 = 0.f, sum1 = 0.f;
        float l10 = 0.f, l11 = 0.f;
        float es0 = 0.f, es1 = 0.f;

        // Alignment peel to 16B (row base only 4B-aligned: C odd)
        const int mis = (int)(((uintptr_t)rp >> 2) & 3);
        const int pre = (4 - mis) & 3;
        if (tid < pre) elem(__ldg(rp + tid), sum0, l10, es0);

        const float4* rp4 = (const float4*)(rp + pre);
        const int n4 = (C - pre) >> 2;

        // Hot region: 8 independent LDG.128 in flight per thread (4 KB/warp)
        #pragma unroll 1
        for (int it = 0; it < FULL_ITERS; ++it) {
            const int i = it * (8 * THREADS) + tid;
            float4 a = __ldcs(rp4 + i);
            float4 b = __ldcs(rp4 + i + THREADS);
            float4 c = __ldcs(rp4 + i + 2 * THREADS);
            float4 d = __ldcs(rp4 + i + 3 * THREADS);
            float4 e = __ldcs(rp4 + i + 4 * THREADS);
            float4 f = __ldcs(rp4 + i + 5 * THREADS);
            float4 h = __ldcs(rp4 + i + 6 * THREADS);
            float4 k = __ldcs(rp4 + i + 7 * THREADS);
            elem4(a, sum0, sum1, l10, l11, es0, es1);
            elem4(b, sum0, sum1, l10, l11, es0, es1);
            elem4(c, sum0, sum1, l10, l11, es0, es1);
            elem4(d, sum0, sum1, l10, l11, es0, es1);
            elem4(e, sum0, sum1, l10, l11, es0, es1);
            elem4(f, sum0, sum1, l10, l11, es0, es1);
            elem4(h, sum0, sum1, l10, l11, es0, es1);
            elem4(k, sum0, sum1, l10, l11, es0, es1);
        }
        // Remainder float4s (< THREADS of them after the 12288 hot region)
        for (int i = FULL_F4 + tid; i < n4; i += THREADS) {
            float4 a = __ldcs(rp4 + i);
            elem4(a, sum0, sum1, l10, l11, es0, es1);
        }
        // Scalar tail (< 4 elems)
        const int tail_start = pre + (n4 << 2);
        if (tid < C - tail_start) elem(__ldg(rp + tail_start + tid), sum0, l10, es0);

        // Shuffle-based block reduction (1 barrier)
        float s = wred(sum0 + sum1);
        float l = wred(l10 + l11);
        float e = wred(es0 + es1);
        if (lane == 0) { sh_a[wid] = s; sh_b[wid] = l; sh_c[wid] = e; }
        __syncthreads();

        if (wid == 0) {
            float rs = (lane < NWARP) ? sh_a[lane] : 0.f;
            float rl = (lane < NWARP) ? sh_b[lane] : 0.f;
            float re = (lane < NWARP) ? sh_c[lane] : 0.f;
            rs = wred(rs); rl = wred(rl); re = wred(re);

            if (lane == 0) {
                // remove generic term at label column, add the real one
                const float wrong = fabsf(1.f - fmaxf(g, 0.f));   // unscaled
                const float mean = rs * (1.f / (float)C);
                const float row_val = fmaxf(fabsf(mean), fabsf(g)) * 10.f;
                const float temp_out_lbl = (g > 0.f) ? -10.f * g : 0.f;
                const float right = fabsf(temp_out_lbl - row_val);
                g_l1[row] = (rl - wrong) * 10.f + right;
                g_ce[row] = logf(re) - g;
            }
        }
        __syncthreads();   // protect shared reuse next row iteration
    }

    // Completion: last of NBLK blocks does the deterministic final reduce
    __shared__ bool s_last;
    if (tid == 0) {
        __threadfence();
        s_last = (atomicInc(&g_count, NBLK - 1) == NBLK - 1);
    }
    __syncthreads();

    if (s_last) {
        float a = 0.f, b = 0.f;
        #pragma unroll
        for (int k = 0; k < B / THREADS; k++) {
            a += g_l1[tid + k * THREADS];
            b += g_ce[tid + k * THREADS];
        }
        __shared__ float fa[NWARP];
        __shared__ float fb[NWARP];
        a = wred(a);
        b = wred(b);
        if (lane == 0) { fa[wid] = a; fb[wid] = b; }
        __syncthreads();
        if (wid == 0) {
            float ra = (lane < NWARP) ? fa[lane] : 0.f;
            float rb = (lane < NWARP) ? fb[lane] : 0.f;
            ra = wred(ra); rb = wred(rb);
            if (lane == 0) {
                const float l1_mean = ra / ((float)B * (float)C);
                const float ce_mean = rb / (float)B;
                res[0] = 0.5f * l1_mean + 0.5f * ce_mean;
            }
        }
    }
}

extern "C" void kernel_launch(void* const* d_in, const int* in_sizes, int n_in,
                              void* d_out, int out_size) {
    const float* out = (const float*)d_in[0];
    const int* labels = (const int*)d_in[1];
    float* res = (float*)d_out;

    fused_kernel<<<NBLK, THREADS>>>(out, labels, res);
}